// round 15
// baseline (speedup 1.0000x reference)
#include <cuda_runtime.h>
#include <cuda_bf16.h>
#include <math.h>
#include <stdint.h>

#define L      1024
#define DM     768
#define DI     1536
#define NH     12
#define HD     128
#define DS     64
#define NPROJ  4620
#define OFF_X  1536
#define OFF_B  3072
#define OFF_C  3840
#define OFF_DT 4608
#define NC     16
#define CT     64
#define DSP    (DS + 4)
#define KSPLIT 3

// ---------------- scratch -------------------------------------------------------
__device__ float g_proj [L * NPROJ];
__device__ float g_xconv[L * DI];
__device__ float g_dtraw[NH * L];
__device__ float g_dt   [NH * L];
__device__ float g_eneg [NH * L];
__device__ float g_ephi [NH * L];
__device__ float g_yssm [L * DI];
__device__ float g_dS   [NH * NC * DS * HD];
__device__ float g_S    [NH * NC * DS * HD];
__device__ float g_out_p[KSPLIT * L * DM];
__device__ __nv_bfloat16 g_xh [L * DM],    g_xl [L * DM];
__device__ __nv_bfloat16 g_w1h[NPROJ*DM],  g_w1l[NPROJ*DM];
__device__ __nv_bfloat16 g_yh [L * DI],    g_yl [L * DI];
__device__ __nv_bfloat16 g_w2h[DM * DI],   g_w2l[DM * DI];

// ---------------- helpers -------------------------------------------------------
__device__ __forceinline__ uint32_t smem_u32(const void* p) {
    uint32_t a;
    asm("{ .reg .u64 t; cvta.to.shared.u64 t, %1; cvt.u32.u64 %0, t; }" : "=r"(a) : "l"(p));
    return a;
}
__device__ __forceinline__ void cp16(uint32_t dst, const void* src) {
    asm volatile("cp.async.cg.shared.global [%0], [%1], 16;" :: "r"(dst), "l"(src));
}
#define CP_COMMIT() asm volatile("cp.async.commit_group;" ::: "memory")
#define CP_WAIT(n)  asm volatile("cp.async.wait_group %0;" :: "n"(n) : "memory")

__device__ __forceinline__ void mma_bf16(float* d, const uint32_t* a,
                                         uint32_t b0, uint32_t b1) {
    asm volatile(
        "mma.sync.aligned.m16n8k16.row.col.f32.bf16.bf16.f32 "
        "{%0,%1,%2,%3},{%4,%5,%6,%7},{%8,%9},{%0,%1,%2,%3};"
        : "+f"(d[0]), "+f"(d[1]), "+f"(d[2]), "+f"(d[3])
        : "r"(a[0]), "r"(a[1]), "r"(a[2]), "r"(a[3]), "r"(b0), "r"(b1));
}
__device__ __forceinline__ void ldsm4(uint32_t* r, uint32_t addr) {
    asm volatile("ldmatrix.sync.aligned.m8n8.x4.shared.b16 {%0,%1,%2,%3}, [%4];"
                 : "=r"(r[0]), "=r"(r[1]), "=r"(r[2]), "=r"(r[3]) : "r"(addr));
}
__device__ __forceinline__ uint32_t pack_bf2(float a, float b) {
    __nv_bfloat162 v = __floats2bfloat162_rn(a, b);
    return *(uint32_t*)&v;
}

// ---------------- fused split (vectorized 8 elems/thread) -----------------------
#define NS1 (L*DM)
#define NS2 (NPROJ*DM)
#define NS3 (DM*DI)
#define NTOT (NS1+NS2+NS3)
__global__ void split3_kernel(const float* __restrict__ x,
                              const float* __restrict__ W_in,
                              const float* __restrict__ W_out)
{
    long i = ((long)blockIdx.x * blockDim.x + threadIdx.x) * 8;
    if (i >= NTOT) return;
    const float* src; __nv_bfloat16 *hi, *lo; long j;
    if (i < NS1)          { src = x;     hi = g_xh;  lo = g_xl;  j = i; }
    else if (i < NS1+NS2) { src = W_in;  hi = g_w1h; lo = g_w1l; j = i - NS1; }
    else                  { src = W_out; hi = g_w2h; lo = g_w2l; j = i - NS1 - NS2; }
    float4 a = *(const float4*)&src[j];
    float4 b = *(const float4*)&src[j + 4];
    float v[8] = {a.x, a.y, a.z, a.w, b.x, b.y, b.z, b.w};
    __nv_bfloat16 h[8];
    float l[8];
#pragma unroll
    for (int k = 0; k < 8; k++) {
        h[k] = __float2bfloat16(v[k]);
        l[k] = v[k] - __bfloat162float(h[k]);
    }
    uint4 hv, lv;
    hv.x = pack_bf2(__bfloat162float(h[0]), __bfloat162float(h[1]));
    hv.y = pack_bf2(__bfloat162float(h[2]), __bfloat162float(h[3]));
    hv.z = pack_bf2(__bfloat162float(h[4]), __bfloat162float(h[5]));
    hv.w = pack_bf2(__bfloat162float(h[6]), __bfloat162float(h[7]));
    lv.x = pack_bf2(l[0], l[1]);
    lv.y = pack_bf2(l[2], l[3]);
    lv.z = pack_bf2(l[4], l[5]);
    lv.w = pack_bf2(l[6], l[7]);
    *(uint4*)&hi[j] = hv;
    *(uint4*)&lo[j] = lv;
}

// ---------------- dt GEMV: dtraw[h][t] = x[t] . W_in[OFF_DT+h] -------------------
// grid (NH, 8), block 256 = 8 warps x 16 t each.
__global__ __launch_bounds__(256)
void dt_gemv_kernel(const float* __restrict__ x, const float* __restrict__ W_in)
{
    const int h = blockIdx.x;
    const int tbase = blockIdx.y * 128;
    __shared__ float wrow[DM];
    for (int k = threadIdx.x; k < DM; k += 256)
        wrow[k] = W_in[(size_t)(OFF_DT + h) * DM + k];
    __syncthreads();
    const int w = threadIdx.x >> 5, lane = threadIdx.x & 31;
#pragma unroll
    for (int i = 0; i < 16; i++) {
        const int t = tbase + w * 16 + i;
        const float* xr = &x[(size_t)t * DM];
        float s = 0.f;
        for (int k = lane * 4; k < DM; k += 128) {
            float4 xv = *(const float4*)&xr[k];
            float4 wv = *(const float4*)&wrow[k];
            s = fmaf(xv.x, wv.x, fmaf(xv.y, wv.y, fmaf(xv.z, wv.z, fmaf(xv.w, wv.w, s))));
        }
#pragma unroll
        for (int o = 16; o > 0; o >>= 1)
            s += __shfl_xor_sync(0xffffffffu, s, o);
        if (lane == 0) g_dtraw[h*L + t] = s;
    }
}

// ---------------- dt / Phi scan (block per head) ---------------------------------
__global__ __launch_bounds__(256)
void dt_phi_kernel(const float* __restrict__ A_log,
                   const float* __restrict__ dt_bias)
{
    const int h   = blockIdx.x;
    const int tid = threadIdx.x;
    const int lane = tid & 31;
    const int w    = tid >> 5;
    const float Ah   = -expf(A_log[h]);
    const float bias = dt_bias[h];
    __shared__ float wsum[8];

    const int t0 = tid * 4;
    float dt[4];
    float loc = 0.f;
#pragma unroll
    for (int i = 0; i < 4; i++) {
        float xr = g_dtraw[h*L + t0 + i];
        dt[i] = fmaxf(xr, 0.f) + log1pf(expf(-fabsf(xr))) + bias;
        g_dt[h*L + t0 + i] = dt[i];
        loc += Ah * dt[i];
    }
    float s = loc;
#pragma unroll
    for (int o = 1; o < 32; o <<= 1) {
        float v = __shfl_up_sync(0xffffffffu, s, o);
        if (lane >= o) s += v;
    }
    if (lane == 31) wsum[w] = s;
    __syncthreads();
    float wexcl = 0.f;
#pragma unroll
    for (int i = 0; i < 7; i++)
        if (i < w) wexcl += wsum[i];
    float run = wexcl + (s - loc);
#pragma unroll
    for (int i = 0; i < 4; i++) {
        run += Ah * dt[i];
        g_eneg[h*L + t0 + i] = expf(fminf(-run, 80.f));
        g_ephi[h*L + t0 + i] = expf(run);
    }
}

// ---------------- bf16 3-term mma GEMM (liveness-aware tile skip) ---------------
#define GSTRIDE_B 80
#define ARR_B_BYTES (128 * GSTRIDE_B)        // 10240

template<int MA>
__global__ __launch_bounds__(256)
void bf16_gemm_nt(int M, int N, int K, int ldk,
                  const __nv_bfloat16* __restrict__ Ahi, const __nv_bfloat16* __restrict__ Alo,
                  const __nv_bfloat16* __restrict__ Bhi, const __nv_bfloat16* __restrict__ Blo,
                  float* __restrict__ C, const float* __restrict__ live)
{
    constexpr int BM        = 32 * MA;
    constexpr int ARR_A     = BM * GSTRIDE_B;
    constexpr int STAGE     = 2 * ARR_A + 2 * ARR_B_BYTES;
    constexpr int OFF_AH    = 0;
    constexpr int OFF_AL    = ARR_A;
    constexpr int OFF_BH    = 2 * ARR_A;
    constexpr int OFF_BL    = 2 * ARR_A + ARR_B_BYTES;

    const long m0 = (long)blockIdx.y * BM;
    const long n0 = (long)blockIdx.x * 128;

    // Liveness skip (GEMM1 only): x-tiles 24..35 are pure B/C columns owned by
    // two heads; dead for this whole t-range iff ephi[h*L+m0]==0 (decreasing).
    // x-tile 36 is pure dt columns — never read (dt comes from the GEMV path).
    if (live) {
        const int bx = blockIdx.x;
        if (bx >= 24) {
            if (bx >= 36) return;
            const int r  = bx - 24;
            const int hh = (r < 6) ? 2*r : 2*(r - 6);
            if (live[hh*L + m0] == 0.f && live[(hh+1)*L + m0] == 0.f) return;
        }
    }

    const long koff = (long)blockIdx.z * K;
    Ahi += koff; Alo += koff; Bhi += koff; Blo += koff;
    C   += (long)blockIdx.z * M * N;

    extern __shared__ char smem[];
    const uint32_t sb = smem_u32(smem);

    const int tid    = threadIdx.x;
    const int lane   = tid & 31;
    const int wid    = tid >> 5;
    const int g      = lane >> 2;
    const int tg     = lane & 3;
    const int lr     = lane & 7;
    const int q      = lane >> 3;
    const int warp_m = wid >> 2;
    const int warp_n = wid & 3;

    uint32_t aoff[MA][2];
#pragma unroll
    for (int ma = 0; ma < MA; ma++) {
        const int rr = warp_m * (MA * 16) + ma * 16;
#pragma unroll
        for (int ka = 0; ka < 2; ka++)
            aoff[ma][ka] = (uint32_t)((rr + lr + (q & 1) * 8) * GSTRIDE_B + ka * 32 + (q >> 1) * 16);
    }
    uint32_t boff[2][2];
#pragma unroll
    for (int na2 = 0; na2 < 2; na2++) {
        const int cc = warp_n * 32 + na2 * 16;
#pragma unroll
        for (int ka = 0; ka < 2; ka++)
            boff[na2][ka] = (uint32_t)((cc + lr + (q >> 1) * 8) * GSTRIDE_B + ka * 32 + (q & 1) * 16);
    }

    const int nchunk = K >> 5;

    float d[MA][4][4];
#pragma unroll
    for (int i = 0; i < MA; i++)
#pragma unroll
        for (int j = 0; j < 4; j++)
#pragma unroll
            for (int r = 0; r < 4; r++) d[i][j][r] = 0.f;

    auto issue_stage = [&](int kc) {
        const int k0 = kc << 5;
        const uint32_t base = sb + (kc % 3) * STAGE;
#pragma unroll
        for (int c = tid; c < 4 * BM; c += 256) {
            const int r = c >> 2, col = (c & 3) * 8;
            cp16(base + OFF_AH + r*GSTRIDE_B + col*2, &Ahi[(m0 + r) * ldk + k0 + col]);
            cp16(base + OFF_AL + r*GSTRIDE_B + col*2, &Alo[(m0 + r) * ldk + k0 + col]);
        }
#pragma unroll
        for (int c = tid; c < 512; c += 256) {
            const int r = c >> 2, col = (c & 3) * 8;
            const long nr = (n0 + r < N) ? (n0 + r) : (N - 1);
            cp16(base + OFF_BH + r*GSTRIDE_B + col*2, &Bhi[nr * ldk + k0 + col]);
            cp16(base + OFF_BL + r*GSTRIDE_B + col*2, &Blo[nr * ldk + k0 + col]);
        }
        CP_COMMIT();
    };

    issue_stage(0);
    if (nchunk > 1) issue_stage(1);

    for (int kc = 0; kc < nchunk; kc++) {
        __syncthreads();
        if (kc + 2 < nchunk) { issue_stage(kc + 2); CP_WAIT(2); }
        else if (kc + 1 < nchunk) { CP_WAIT(1); }
        else { CP_WAIT(0); }
        __syncthreads();

        const uint32_t st  = sb + (kc % 3) * STAGE;
        const uint32_t pAh = st + OFF_AH;
        const uint32_t pAl = st + OFF_AL;
        const uint32_t pBh = st + OFF_BH;
        const uint32_t pBl = st + OFF_BL;

#pragma unroll
        for (int ka = 0; ka < 2; ka++) {
            uint32_t ah[MA][4], al[MA][4];
#pragma unroll
            for (int ma = 0; ma < MA; ma++) {
                ldsm4(ah[ma], pAh + aoff[ma][ka]);
                ldsm4(al[ma], pAl + aoff[ma][ka]);
            }
            uint32_t bh[4][2], bl[4][2];
#pragma unroll
            for (int na2 = 0; na2 < 2; na2++) {
                uint32_t th[4], tl[4];
                ldsm4(th, pBh + boff[na2][ka]);
                ldsm4(tl, pBl + boff[na2][ka]);
                bh[na2*2][0] = th[0]; bh[na2*2][1] = th[1];
                bh[na2*2+1][0] = th[2]; bh[na2*2+1][1] = th[3];
                bl[na2*2][0] = tl[0]; bl[na2*2][1] = tl[1];
                bl[na2*2+1][0] = tl[2]; bl[na2*2+1][1] = tl[3];
            }
#pragma unroll
            for (int na = 0; na < 4; na++)
#pragma unroll
                for (int ma = 0; ma < MA; ma++)
                    mma_bf16(d[ma][na], ah[ma], bh[na][0], bh[na][1]);
#pragma unroll
            for (int na = 0; na < 4; na++)
#pragma unroll
                for (int ma = 0; ma < MA; ma++)
                    mma_bf16(d[ma][na], al[ma], bh[na][0], bh[na][1]);
#pragma unroll
            for (int na = 0; na < 4; na++)
#pragma unroll
                for (int ma = 0; ma < MA; ma++)
                    mma_bf16(d[ma][na], ah[ma], bl[na][0], bl[na][1]);
        }
    }

#pragma unroll
    for (int ma = 0; ma < MA; ma++) {
        const long rbase = m0 + warp_m * (MA * 16) + ma * 16;
#pragma unroll
        for (int na = 0; na < 4; na++) {
            const long col = n0 + warp_n * 32 + na * 8 + 2 * tg;
            if (col < N) {
                *(float2*)&C[(rbase + g    ) * N + col] = make_float2(d[ma][na][0], d[ma][na][1]);
                *(float2*)&C[(rbase + g + 8) * N + col] = make_float2(d[ma][na][2], d[ma][na][3]);
            }
        }
    }
}

// ---------------- split-K combine -----------------------------------------------
__global__ void combine_kernel(float* __restrict__ out)
{
    int i = blockIdx.x * blockDim.x + threadIdx.x;
    if (i < L * DM)
        out[i] = (g_out_p[i] + g_out_p[i + L*DM]) + g_out_p[i + 2*L*DM];
}

// ---------------- conv1d+silu (vectorized) --------------------------------------
#define CONVBLKS (L * (DI/4) / 256)          // 1536
__global__ __launch_bounds__(256)
void conv_silu_kernel(const float* __restrict__ conv_w,
                      const float* __restrict__ conv_b)
{
    int id = blockIdx.x * 256 + threadIdx.x;
    int t = id / (DI/4);
    int c = (id % (DI/4)) * 4;
    float4 acc = *(const float4*)&conv_b[c];
#pragma unroll
    for (int i = 0; i < 4; i++) {
        int ts = t + i - 3;
        if (ts >= 0) {
            float4 xv = *(const float4*)&g_proj[(size_t)ts * NPROJ + OFF_X + c];
            acc.x = fmaf(xv.x, conv_w[(c+0)*4 + i], acc.x);
            acc.y = fmaf(xv.y, conv_w[(c+1)*4 + i], acc.y);
            acc.z = fmaf(xv.z, conv_w[(c+2)*4 + i], acc.z);
            acc.w = fmaf(xv.w, conv_w[(c+3)*4 + i], acc.w);
        }
    }
    float4 o;
    o.x = acc.x / (1.f + expf(-acc.x));
    o.y = acc.y / (1.f + expf(-acc.y));
    o.z = acc.z / (1.f + expf(-acc.z));
    o.w = acc.w / (1.f + expf(-acc.w));
    *(float4*)&g_xconv[(size_t)t * DI + c] = o;
}

// ---------------- SSD stage A: head-dim 2-way split + liveness early-exit -------
__global__ __launch_bounds__(256)
void chunk_dstate_kernel()
{
    const int h = blockIdx.x;
    const int c = blockIdx.y;
    if (c == NC - 1) return;
    if (g_ephi[h*L + (c+1)*CT] == 0.f) return;

    const int z = blockIdx.z;
    const int t0 = c * CT;
    const int ib = z * 64;

    __shared__ float Bsh[CT][DS];
    __shared__ float Xsh[CT][64];

    const int tid = threadIdx.x;
    for (int idx = tid*4; idx < CT*DS; idx += 256*4) {
        int u = idx / DS, j = idx % DS;
        *(float4*)&Bsh[u][j] =
            *(const float4*)&g_proj[(size_t)(t0+u)*NPROJ + OFF_B + h*DS + j];
    }
    for (int idx = tid*4; idx < CT*64; idx += 256*4) {
        int u = idx / 64, i = idx % 64;
        float su = g_eneg[h*L + t0 + u] * g_dt[h*L + t0 + u];
        float4 xv = *(const float4*)&g_xconv[(size_t)(t0+u)*DI + h*HD + ib + i];
        xv.x *= su; xv.y *= su; xv.z *= su; xv.w *= su;
        *(float4*)&Xsh[u][i] = xv;
    }
    __syncthreads();

    const int lane = tid & 31;
    const int w    = tid >> 5;
    const int j0   = (w * 2 + (lane >> 4)) * 4;
    const int i0   = (lane & 15) * 4;

    float acc[4][4];
#pragma unroll
    for (int a = 0; a < 4; a++)
#pragma unroll
        for (int b = 0; b < 4; b++) acc[a][b] = 0.f;

    for (int u = 0; u < CT; u++) {
        float4 xv = *(const float4*)&Xsh[u][i0];
#pragma unroll
        for (int a = 0; a < 4; a++) {
            float bj = Bsh[u][j0 + a];
            acc[a][0] = fmaf(bj, xv.x, acc[a][0]);
            acc[a][1] = fmaf(bj, xv.y, acc[a][1]);
            acc[a][2] = fmaf(bj, xv.z, acc[a][2]);
            acc[a][3] = fmaf(bj, xv.w, acc[a][3]);
        }
    }
    float* dst = &g_dS[((size_t)(h*NC + c)) * DS * HD];
#pragma unroll
    for (int a = 0; a < 4; a++)
        *(float4*)&dst[(j0+a)*HD + ib + i0] = *(float4*)&acc[a][0];
}

// ---------------- SSD stage B: prefix with liveness break ------------------------
__global__ void state_prefix_kernel()
{
    int g = blockIdx.x * blockDim.x + threadIdx.x;
    if (g >= NH * DS * HD) return;
    int h = g / (DS*HD);
    int e = g % (DS*HD);
    float run = 0.f;
    for (int c = 0; c < NC; c++) {
        if (g_ephi[h*L + c*CT] == 0.f) break;
        size_t idx = ((size_t)(h*NC + c)) * DS * HD + e;
        g_S[idx] = run;
        run += g_dS[idx];
    }
}

// ---------------- SSD stage C: 2-way t-split + dead-block fast path -------------
__global__ __launch_bounds__(256)
void ssd_output_kernel(const float* __restrict__ Dp)
{
    const int h = blockIdx.x;
    const int c = blockIdx.y;
    const int z = blockIdx.z;
    const int t0 = c * CT;
    const int tz = z * 32;

    if (g_ephi[h*L + t0 + tz] == 0.f) {
        const int lane = threadIdx.x & 31;
        const int tg   = threadIdx.x >> 5;
        const int tb   = tg * 4;
        const int i0   = lane * 4;
        const int hbase = h * HD;
        const float dph = Dp[h];
#pragma unroll
        for (int s = 0; s < 4; s++) {
            int t = t0 + tz + tb + s;
            float4 xv = *(const float4*)&g_xconv[(size_t)t * DI + hbase + i0];
            float4 y = make_float4(dph * xv.x, dph * xv.y, dph * xv.z, dph * xv.w);
            *(float4*)&g_yssm[(size_t)t * DI + hbase + i0] = y;
        }
        return;
    }

    __shared__ float Csh [32][DSP];
    __shared__ float BGsh[CT][DSP];
    __shared__ float sphi[32], scoef[CT];

    const int tid = threadIdx.x;
    for (int idx = tid*4; idx < 32*DS; idx += 256*4) {
        int tl = idx / DS, j = idx % DS;
        *(float4*)&Csh[tl][j] =
            *(const float4*)&g_proj[(size_t)(t0+tz+tl)*NPROJ + OFF_C + h*DS + j];
    }
    for (int idx = tid*4; idx < CT*DS; idx += 256*4) {
        int u = idx / DS, j = idx % DS;
        *(float4*)&BGsh[u][j] =
            *(const float4*)&g_proj[(size_t)(t0+u)*NPROJ + OFF_B + h*DS + j];
    }
    if (tid < 32)
        sphi[tid] = g_ephi[h*L + t0 + tz + tid];
    if (tid < CT)
        scoef[tid] = g_eneg[h*L + t0 + tid] * g_dt[h*L + t0 + tid];
    __syncthreads();

    const int ulim = z ? CT : 32;

    {
        const int ut = tid & 15;
        const int tt = tid >> 4;
        const int ta = tt * 2;
        const int ua = ut * 4;
        float gacc[2][4];
#pragma unroll
        for (int a = 0; a < 2; a++)
#pragma unroll
            for (int b = 0; b < 4; b++) gacc[a][b] = 0.f;
        if (ua < ulim) {
            for (int k = 0; k < DS; k++) {
                float cr[2], br[4];
#pragma unroll
                for (int a = 0; a < 2; a++) cr[a] = Csh [ta+a][k];
#pragma unroll
                for (int b = 0; b < 4; b++) br[b] = BGsh[ua+b][k];
#pragma unroll
                for (int a = 0; a < 2; a++)
#pragma unroll
                    for (int b = 0; b < 4; b++)
                        gacc[a][b] = fmaf(cr[a], br[b], gacc[a][b]);
            }
        }
        __syncthreads();
#pragma unroll
        for (int a = 0; a < 2; a++)
#pragma unroll
            for (int b = 0; b < 4; b++) {
                int tl = ta + a, u = ua + b;
                float m = (tz + tl >= u) ? sphi[tl] * scoef[u] : 0.f;
                BGsh[tl][u] = m * gacc[a][b];
            }
        __syncthreads();
    }

    const int lane = tid & 31;
    const int tg   = tid >> 5;
    const int tb   = tg * 4;
    const int i0   = lane * 4;
    const int hbase = h * HD;
    const float dph = Dp[h];
    const float* Srow = &g_S[((size_t)(h*NC + c)) * DS * HD];

    float accI[4][4], accS[4][4];
#pragma unroll
    for (int s = 0; s < 4; s++)
#pragma unroll
        for (int b = 0; b < 4; b++) { accI[s][b] = 0.f; accS[s][b] = 0.f; }

    for (int u = 0; u < ulim; u++) {
        float4 xv = *(const float4*)&g_xconv[(size_t)(t0+u)*DI + hbase + i0];
#pragma unroll
        for (int s = 0; s < 4; s++) {
            float gv = BGsh[tb+s][u];
            accI[s][0] = fmaf(gv, xv.x, accI[s][0]);
            accI[s][1] = fmaf(gv, xv.y, accI[s][1]);
            accI[s][2] = fmaf(gv, xv.z, accI[s][2]);
            accI[s][3] = fmaf(gv, xv.w, accI[s][3]);
        }
    }
    for (int j = 0; j < DS; j++) {
        float4 sv = *(const float4*)&Srow[j*HD + i0];
#pragma unroll
        for (int s = 0; s < 4; s++) {
            float cj = Csh[tb+s][j];
            accS[s][0] = fmaf(cj, sv.x, accS[s][0]);
            accS[s][1] = fmaf(cj, sv.y, accS[s][1]);
            accS[s][2] = fmaf(cj, sv.z, accS[s][2]);
            accS[s][3] = fmaf(cj, sv.w, accS[s][3]);
        }
    }
#pragma unroll
    for (int s = 0; s < 4; s++) {
        int t = t0 + tz + tb + s;
        float p = sphi[tb + s];
        float4 xv = *(const float4*)&g_xconv[(size_t)t * DI + hbase + i0];
        float4 y;
        y.x = fmaf(p, accS[s][0], accI[s][0]) + dph * xv.x;
        y.y = fmaf(p, accS[s][1], accI[s][1]) + dph * xv.y;
        y.z = fmaf(p, accS[s][2], accI[s][2]) + dph * xv.z;
        y.w = fmaf(p, accS[s][3], accI[s][3]) + dph * xv.w;
        *(float4*)&g_yssm[(size_t)t * DI + hbase + i0] = y;
    }
}

// ---------------- RMS norm + gate + bf16 split (vectorized) ---------------------
__global__ void rms_gate_kernel(const float* __restrict__ norm_w)
{
    const int t = blockIdx.x;
    __shared__ float red[256];
    float s = 0.f;
    for (int idx = threadIdx.x; idx < DI/4; idx += 256) {
        float4 v = *(const float4*)&g_yssm[(size_t)t * DI + idx*4];
        s = fmaf(v.x, v.x, s); s = fmaf(v.y, v.y, s);
        s = fmaf(v.z, v.z, s); s = fmaf(v.w, v.w, s);
    }
    red[threadIdx.x] = s;
    __syncthreads();
    for (int o = 128; o > 0; o >>= 1) {
        if (threadIdx.x < o) red[threadIdx.x] += red[threadIdx.x + o];
        __syncthreads();
    }
    float rms = rsqrtf(red[0] / (float)DI + 1e-5f);
    for (int idx = threadIdx.x; idx < DI/4; idx += 256) {
        const int c = idx * 4;
        float4 v  = *(const float4*)&g_yssm[(size_t)t * DI + c];
        float4 z4 = *(const float4*)&g_proj[(size_t)t * NPROJ + c];
        float4 w4 = *(const float4*)&norm_w[c];
        float yb[4];
        yb[0] = v.x * rms * w4.x * (z4.x / (1.f + expf(-z4.x)));
        yb[1] = v.y * rms * w4.y * (z4.y / (1.f + expf(-z4.y)));
        yb[2] = v.z * rms * w4.z * (z4.z / (1.f + expf(-z4.z)));
        yb[3] = v.w * rms * w4.w * (z4.w / (1.f + expf(-z4.w)));
        __nv_bfloat16 h[4];
        float l[4];
#pragma unroll
        for (int k = 0; k < 4; k++) {
            h[k] = __float2bfloat16(yb[k]);
            l[k] = yb[k] - __bfloat162float(h[k]);
        }
        uint2 hv, lv;
        hv.x = pack_bf2(__bfloat162float(h[0]), __bfloat162float(h[1]));
        hv.y = pack_bf2(__bfloat162float(h[2]), __bfloat162float(h[3]));
        lv.x = pack_bf2(l[0], l[1]);
        lv.y = pack_bf2(l[2], l[3]);
        *(uint2*)&g_yh[(size_t)t * DI + c] = hv;
        *(uint2*)&g_yl[(size_t)t * DI + c] = lv;
    }
}

// ---------------- launch --------------------------------------------------------
extern "C" void kernel_launch(void* const* d_in, const int* in_sizes, int n_in,
                              void* d_out, int out_size)
{
    const float* x       = (const float*)d_in[0];
    const float* W_in    = (const float*)d_in[1];
    const float* conv_w  = (const float*)d_in[2];
    const float* conv_b  = (const float*)d_in[3];
    const float* A_log   = (const float*)d_in[4];
    const float* Dp      = (const float*)d_in[5];
    const float* dt_bias = (const float*)d_in[6];
    const float* W_out   = (const float*)d_in[7];
    const float* norm_w  = (const float*)d_in[8];
    float* out = (float*)d_out;

    float *proj_p, *outp_p, *ephi_p;
    __nv_bfloat16 *xh, *xl, *w1h, *w1l, *yh, *yl, *w2h, *w2l;
    cudaGetSymbolAddress((void**)&proj_p, g_proj);
    cudaGetSymbolAddress((void**)&outp_p, g_out_p);
    cudaGetSymbolAddress((void**)&ephi_p, g_ephi);
    cudaGetSymbolAddress((void**)&xh,  g_xh);  cudaGetSymbolAddress((void**)&xl,  g_xl);
    cudaGetSymbolAddress((void**)&w1h, g_w1h); cudaGetSymbolAddress((void**)&w1l, g_w1l);
    cudaGetSymbolAddress((void**)&yh,  g_yh);  cudaGetSymbolAddress((void**)&yl,  g_yl);
    cudaGetSymbolAddress((void**)&w2h, g_w2h); cudaGetSymbolAddress((void**)&w2l, g_w2l);

    constexpr int SMEM_MA4 = 3 * (2 * 128*GSTRIDE_B + 2 * ARR_B_BYTES);  // 122880
    constexpr int SMEM_MA2 = 3 * (2 *  64*GSTRIDE_B + 2 * ARR_B_BYTES);  //  92160
    cudaFuncSetAttribute(bf16_gemm_nt<4>, cudaFuncAttributeMaxDynamicSharedMemorySize, SMEM_MA4);
    cudaFuncSetAttribute(bf16_gemm_nt<2>, cudaFuncAttributeMaxDynamicSharedMemorySize, SMEM_MA2);

    // 0a) dt GEMV + Phi scan (fp32, independent of splits/GEMM1)
    dt_gemv_kernel<<<dim3(NH, 8), 256>>>(x, W_in);
    dt_phi_kernel<<<NH, 256>>>(A_log, dt_bias);

    // 0b) fused bf16 hi/lo splits
    split3_kernel<<<(NTOT/8 + 255)/256, 256>>>(x, W_in, W_out);

    // 1) proj = x @ W_in^T with dead-tile skip (B/C columns for dead t; dt cols)
    bf16_gemm_nt<4><<<dim3((NPROJ + 127)/128, L/128, 1), 256, SMEM_MA4>>>(
        L, NPROJ, DM, DM, xh, xl, w1h, w1l, proj_p, ephi_p);

    // 2) conv + silu
    conv_silu_kernel<<<CONVBLKS, 256>>>(conv_w, conv_b);

    // 3) SSD pipeline with liveness early-exits
    chunk_dstate_kernel<<<dim3(NH, NC, 2), 256>>>();
    state_prefix_kernel<<<(NH*DS*HD + 255)/256, 256>>>();
    ssd_output_kernel<<<dim3(NH, NC, 2), 256>>>(Dp);

    // 4) RMS norm + gate + split
    rms_gate_kernel<<<L, 256>>>(norm_w);

    // 5) out = ybar @ W_out^T, split-K=3 + combine
    bf16_gemm_nt<2><<<dim3(DM/128, L/64, KSPLIT), 256, SMEM_MA2>>>(
        L, DM, DI/KSPLIT, DI, yh, yl, w2h, w2l, outp_p, nullptr);
    combine_kernel<<<(L*DM + 255)/256, 256>>>(out);
}

// round 16
// speedup vs baseline: 1.1400x; 1.1400x over previous
#include <cuda_runtime.h>
#include <cuda_bf16.h>
#include <math.h>
#include <stdint.h>

#define L      1024
#define DM     768
#define DI     1536
#define NH     12
#define HD     128
#define DS     64
#define NPROJ  4620
#define OFF_X  1536
#define OFF_B  3072
#define OFF_C  3840
#define OFF_DT 4608
#define NC     16
#define CT     64
#define DSP    (DS + 4)
#define KSPLIT 3

// ---------------- scratch -------------------------------------------------------
__device__ float g_proj [L * NPROJ];
__device__ float g_xconv[L * DI];
__device__ float g_dtraw[NH * L];
__device__ float g_dt   [NH * L];
__device__ float g_eneg [NH * L];
__device__ float g_ephi [NH * L];
__device__ float g_yssm [L * DI];
__device__ float g_dS   [NH * NC * DS * HD];
__device__ float g_S    [NH * NC * DS * HD];
__device__ float g_out_p[KSPLIT * L * DM];
__device__ __nv_bfloat16 g_xh [L * DM],    g_xl [L * DM];
__device__ __nv_bfloat16 g_w1h[NPROJ*DM],  g_w1l[NPROJ*DM];
__device__ __nv_bfloat16 g_yh [L * DI],    g_yl [L * DI];
__device__ __nv_bfloat16 g_w2h[DM * DI],   g_w2l[DM * DI];

// ---------------- helpers -------------------------------------------------------
__device__ __forceinline__ uint32_t smem_u32(const void* p) {
    uint32_t a;
    asm("{ .reg .u64 t; cvta.to.shared.u64 t, %1; cvt.u32.u64 %0, t; }" : "=r"(a) : "l"(p));
    return a;
}
__device__ __forceinline__ void cp16(uint32_t dst, const void* src) {
    asm volatile("cp.async.cg.shared.global [%0], [%1], 16;" :: "r"(dst), "l"(src));
}
#define CP_COMMIT() asm volatile("cp.async.commit_group;" ::: "memory")
#define CP_WAIT(n)  asm volatile("cp.async.wait_group %0;" :: "n"(n) : "memory")

__device__ __forceinline__ void mma_bf16(float* d, const uint32_t* a,
                                         uint32_t b0, uint32_t b1) {
    asm volatile(
        "mma.sync.aligned.m16n8k16.row.col.f32.bf16.bf16.f32 "
        "{%0,%1,%2,%3},{%4,%5,%6,%7},{%8,%9},{%0,%1,%2,%3};"
        : "+f"(d[0]), "+f"(d[1]), "+f"(d[2]), "+f"(d[3])
        : "r"(a[0]), "r"(a[1]), "r"(a[2]), "r"(a[3]), "r"(b0), "r"(b1));
}
__device__ __forceinline__ void ldsm4(uint32_t* r, uint32_t addr) {
    asm volatile("ldmatrix.sync.aligned.m8n8.x4.shared.b16 {%0,%1,%2,%3}, [%4];"
                 : "=r"(r[0]), "=r"(r[1]), "=r"(r[2]), "=r"(r[3]) : "r"(addr));
}
__device__ __forceinline__ uint32_t pack_bf2(float a, float b) {
    __nv_bfloat162 v = __floats2bfloat162_rn(a, b);
    return *(uint32_t*)&v;
}

// ---------------- fused split (vectorized 8 elems/thread) -----------------------
#define NS1 (L*DM)
#define NS2 (NPROJ*DM)
#define NS3 (DM*DI)
#define NTOT (NS1+NS2+NS3)
__global__ void split3_kernel(const float* __restrict__ x,
                              const float* __restrict__ W_in,
                              const float* __restrict__ W_out)
{
    long i = ((long)blockIdx.x * blockDim.x + threadIdx.x) * 8;
    if (i >= NTOT) return;
    const float* src; __nv_bfloat16 *hi, *lo; long j;
    if (i < NS1)          { src = x;     hi = g_xh;  lo = g_xl;  j = i; }
    else if (i < NS1+NS2) { src = W_in;  hi = g_w1h; lo = g_w1l; j = i - NS1; }
    else                  { src = W_out; hi = g_w2h; lo = g_w2l; j = i - NS1 - NS2; }
    float4 a = *(const float4*)&src[j];
    float4 b = *(const float4*)&src[j + 4];
    float v[8] = {a.x, a.y, a.z, a.w, b.x, b.y, b.z, b.w};
    __nv_bfloat16 h[8];
    float l[8];
#pragma unroll
    for (int k = 0; k < 8; k++) {
        h[k] = __float2bfloat16(v[k]);
        l[k] = v[k] - __bfloat162float(h[k]);
    }
    uint4 hv, lv;
    hv.x = pack_bf2(__bfloat162float(h[0]), __bfloat162float(h[1]));
    hv.y = pack_bf2(__bfloat162float(h[2]), __bfloat162float(h[3]));
    hv.z = pack_bf2(__bfloat162float(h[4]), __bfloat162float(h[5]));
    hv.w = pack_bf2(__bfloat162float(h[6]), __bfloat162float(h[7]));
    lv.x = pack_bf2(l[0], l[1]);
    lv.y = pack_bf2(l[2], l[3]);
    lv.z = pack_bf2(l[4], l[5]);
    lv.w = pack_bf2(l[6], l[7]);
    *(uint4*)&hi[j] = hv;
    *(uint4*)&lo[j] = lv;
}

// ---------------- efficient dt GEMV: x read once, W_dt rows in smem -------------
// grid L/64, block 256 (8 warps x 8 t's). dtraw[h][t] = x[t] . W_in[OFF_DT+h].
__global__ __launch_bounds__(256)
void dt_gemv_kernel(const float* __restrict__ x, const float* __restrict__ W_in)
{
    __shared__ float wsm[NH][DM];          // 36 KB
    for (int k = threadIdx.x; k < NH * DM; k += 256)
        wsm[k / DM][k % DM] = W_in[(size_t)OFF_DT * DM + k];
    __syncthreads();

    const int w = threadIdx.x >> 5, lane = threadIdx.x & 31;
    const int tbase = blockIdx.x * 64 + w * 8;
#pragma unroll
    for (int i = 0; i < 8; i++) {
        const int t = tbase + i;
        // lane holds 6 float4 of x[t] (k = lane*4 + 128*j)
        float4 xr[6];
#pragma unroll
        for (int j = 0; j < 6; j++)
            xr[j] = *(const float4*)&x[(size_t)t * DM + lane * 4 + j * 128];
#pragma unroll
        for (int h = 0; h < NH; h++) {
            float s = 0.f;
#pragma unroll
            for (int j = 0; j < 6; j++) {
                float4 wv = *(const float4*)&wsm[h][lane * 4 + j * 128];
                s = fmaf(xr[j].x, wv.x, fmaf(xr[j].y, wv.y,
                    fmaf(xr[j].z, wv.z, fmaf(xr[j].w, wv.w, s))));
            }
#pragma unroll
            for (int o = 16; o > 0; o >>= 1)
                s += __shfl_xor_sync(0xffffffffu, s, o);
            if (lane == 0) g_dtraw[h*L + t] = s;
        }
    }
}

// ---------------- dt / Phi scan (block per head) ---------------------------------
__global__ __launch_bounds__(256)
void dt_phi_kernel(const float* __restrict__ A_log,
                   const float* __restrict__ dt_bias)
{
    const int h   = blockIdx.x;
    const int tid = threadIdx.x;
    const int lane = tid & 31;
    const int w    = tid >> 5;
    const float Ah   = -expf(A_log[h]);
    const float bias = dt_bias[h];
    __shared__ float wsum[8];

    const int t0 = tid * 4;
    float dt[4];
    float loc = 0.f;
#pragma unroll
    for (int i = 0; i < 4; i++) {
        float xr = g_dtraw[h*L + t0 + i];
        dt[i] = fmaxf(xr, 0.f) + log1pf(expf(-fabsf(xr))) + bias;
        g_dt[h*L + t0 + i] = dt[i];
        loc += Ah * dt[i];
    }
    float s = loc;
#pragma unroll
    for (int o = 1; o < 32; o <<= 1) {
        float v = __shfl_up_sync(0xffffffffu, s, o);
        if (lane >= o) s += v;
    }
    if (lane == 31) wsum[w] = s;
    __syncthreads();
    float wexcl = 0.f;
#pragma unroll
    for (int i = 0; i < 7; i++)
        if (i < w) wexcl += wsum[i];
    float run = wexcl + (s - loc);
#pragma unroll
    for (int i = 0; i < 4; i++) {
        run += Ah * dt[i];
        g_eneg[h*L + t0 + i] = expf(fminf(-run, 80.f));
        g_ephi[h*L + t0 + i] = expf(run);
    }
}

// ---------------- bf16 3-term mma GEMM: 64x128 tiles, 2 CTAs/SM, liveness skip --
#define GSTRIDE_B 80
#define BMR       64
#define ARR_A_B   (BMR * GSTRIDE_B)          // 5120
#define ARR_B_B   (128 * GSTRIDE_B)          // 10240
#define STAGE_B   (2*ARR_A_B + 2*ARR_B_B)    // 30720
#define OFF_AH    0
#define OFF_AL    ARR_A_B
#define OFF_BH    (2*ARR_A_B)
#define OFF_BL    (2*ARR_A_B + ARR_B_B)
#define GEMM_SMEM (3 * STAGE_B)              // 92160

__global__ __launch_bounds__(256, 2)
void bf16_gemm_nt(int M, int N, int K, int ldk,
                  const __nv_bfloat16* __restrict__ Ahi, const __nv_bfloat16* __restrict__ Alo,
                  const __nv_bfloat16* __restrict__ Bhi, const __nv_bfloat16* __restrict__ Blo,
                  float* __restrict__ C, const float* __restrict__ live)
{
    const long m0 = (long)blockIdx.y * BMR;
    const long n0 = (long)blockIdx.x * 128;

    // Liveness skip (GEMM1): x-tiles 24..35 are pure B/C columns for 2 heads;
    // dead iff ephi[h*L+m0]==0 for both (ephi decreasing in t).
    // x-tile 36 is dt columns only — dt comes from the GEMV path, never read.
    if (live) {
        const int bx = blockIdx.x;
        if (bx >= 24) {
            if (bx >= 36) return;
            const int r  = bx - 24;
            const int hh = (r < 6) ? 2*r : 2*(r - 6);
            if (live[hh*L + m0] == 0.f && live[(hh+1)*L + m0] == 0.f) return;
        }
    }

    const long koff = (long)blockIdx.z * K;
    Ahi += koff; Alo += koff; Bhi += koff; Blo += koff;
    C   += (long)blockIdx.z * M * N;

    extern __shared__ char smem[];
    const uint32_t sb = smem_u32(smem);

    const int tid    = threadIdx.x;
    const int lane   = tid & 31;
    const int wid    = tid >> 5;
    const int g      = lane >> 2;
    const int tg     = lane & 3;
    const int lr     = lane & 7;
    const int q      = lane >> 3;
    const int warp_m = wid >> 2;
    const int warp_n = wid & 3;

    uint32_t aoff[2][2];
#pragma unroll
    for (int ma = 0; ma < 2; ma++) {
        const int rr = warp_m * 32 + ma * 16;
#pragma unroll
        for (int ka = 0; ka < 2; ka++)
            aoff[ma][ka] = (uint32_t)((rr + lr + (q & 1) * 8) * GSTRIDE_B + ka * 32 + (q >> 1) * 16);
    }
    uint32_t boff[2][2];
#pragma unroll
    for (int na2 = 0; na2 < 2; na2++) {
        const int cc = warp_n * 32 + na2 * 16;
#pragma unroll
        for (int ka = 0; ka < 2; ka++)
            boff[na2][ka] = (uint32_t)((cc + lr + (q >> 1) * 8) * GSTRIDE_B + ka * 32 + (q & 1) * 16);
    }

    const int nchunk = K >> 5;

    float d[2][4][4];
#pragma unroll
    for (int i = 0; i < 2; i++)
#pragma unroll
        for (int j = 0; j < 4; j++)
#pragma unroll
            for (int r = 0; r < 4; r++) d[i][j][r] = 0.f;

    auto issue_stage = [&](int kc) {
        const int k0 = kc << 5;
        const uint32_t base = sb + (kc % 3) * STAGE_B;
        {
            const int r = tid >> 2, col = (tid & 3) * 8;
            cp16(base + OFF_AH + r*GSTRIDE_B + col*2, &Ahi[(m0 + r) * ldk + k0 + col]);
            cp16(base + OFF_AL + r*GSTRIDE_B + col*2, &Alo[(m0 + r) * ldk + k0 + col]);
        }
#pragma unroll
        for (int c = tid; c < 512; c += 256) {
            const int r = c >> 2, col = (c & 3) * 8;
            const long nr = (n0 + r < N) ? (n0 + r) : (N - 1);
            cp16(base + OFF_BH + r*GSTRIDE_B + col*2, &Bhi[nr * ldk + k0 + col]);
            cp16(base + OFF_BL + r*GSTRIDE_B + col*2, &Blo[nr * ldk + k0 + col]);
        }
        CP_COMMIT();
    };

    issue_stage(0);
    if (nchunk > 1) issue_stage(1);

    for (int kc = 0; kc < nchunk; kc++) {
        __syncthreads();
        if (kc + 2 < nchunk) { issue_stage(kc + 2); CP_WAIT(2); }
        else if (kc + 1 < nchunk) { CP_WAIT(1); }
        else { CP_WAIT(0); }
        __syncthreads();

        const uint32_t st  = sb + (kc % 3) * STAGE_B;
        const uint32_t pAh = st + OFF_AH;
        const uint32_t pAl = st + OFF_AL;
        const uint32_t pBh = st + OFF_BH;
        const uint32_t pBl = st + OFF_BL;

#pragma unroll
        for (int ka = 0; ka < 2; ka++) {
            uint32_t ah[2][4], al[2][4];
#pragma unroll
            for (int ma = 0; ma < 2; ma++) {
                ldsm4(ah[ma], pAh + aoff[ma][ka]);
                ldsm4(al[ma], pAl + aoff[ma][ka]);
            }
            uint32_t bh[4][2], bl[4][2];
#pragma unroll
            for (int na2 = 0; na2 < 2; na2++) {
                uint32_t th[4], tl[4];
                ldsm4(th, pBh + boff[na2][ka]);
                ldsm4(tl, pBl + boff[na2][ka]);
                bh[na2*2][0] = th[0]; bh[na2*2][1] = th[1];
                bh[na2*2+1][0] = th[2]; bh[na2*2+1][1] = th[3];
                bl[na2*2][0] = tl[0]; bl[na2*2][1] = tl[1];
                bl[na2*2+1][0] = tl[2]; bl[na2*2+1][1] = tl[3];
            }
#pragma unroll
            for (int na = 0; na < 4; na++)
#pragma unroll
                for (int ma = 0; ma < 2; ma++)
                    mma_bf16(d[ma][na], ah[ma], bh[na][0], bh[na][1]);
#pragma unroll
            for (int na = 0; na < 4; na++)
#pragma unroll
                for (int ma = 0; ma < 2; ma++)
                    mma_bf16(d[ma][na], al[ma], bh[na][0], bh[na][1]);
#pragma unroll
            for (int na = 0; na < 4; na++)
#pragma unroll
                for (int ma = 0; ma < 2; ma++)
                    mma_bf16(d[ma][na], ah[ma], bl[na][0], bl[na][1]);
        }
    }

#pragma unroll
    for (int ma = 0; ma < 2; ma++) {
        const long rbase = m0 + warp_m * 32 + ma * 16;
#pragma unroll
        for (int na = 0; na < 4; na++) {
            const long col = n0 + warp_n * 32 + na * 8 + 2 * tg;
            if (col < N) {
                *(float2*)&C[(rbase + g    ) * N + col] = make_float2(d[ma][na][0], d[ma][na][1]);
                *(float2*)&C[(rbase + g + 8) * N + col] = make_float2(d[ma][na][2], d[ma][na][3]);
            }
        }
    }
}

// ---------------- split-K combine -----------------------------------------------
__global__ void combine_kernel(float* __restrict__ out)
{
    int i = blockIdx.x * blockDim.x + threadIdx.x;
    if (i < L * DM)
        out[i] = (g_out_p[i] + g_out_p[i + L*DM]) + g_out_p[i + 2*L*DM];
}

// ---------------- conv1d+silu (vectorized) --------------------------------------
#define CONVBLKS (L * (DI/4) / 256)          // 1536
__global__ __launch_bounds__(256)
void conv_silu_kernel(const float* __restrict__ conv_w,
                      const float* __restrict__ conv_b)
{
    int id = blockIdx.x * 256 + threadIdx.x;
    int t = id / (DI/4);
    int c = (id % (DI/4)) * 4;
    float4 acc = *(const float4*)&conv_b[c];
#pragma unroll
    for (int i = 0; i < 4; i++) {
        int ts = t + i - 3;
        if (ts >= 0) {
            float4 xv = *(const float4*)&g_proj[(size_t)ts * NPROJ + OFF_X + c];
            acc.x = fmaf(xv.x, conv_w[(c+0)*4 + i], acc.x);
            acc.y = fmaf(xv.y, conv_w[(c+1)*4 + i], acc.y);
            acc.z = fmaf(xv.z, conv_w[(c+2)*4 + i], acc.z);
            acc.w = fmaf(xv.w, conv_w[(c+3)*4 + i], acc.w);
        }
    }
    float4 o;
    o.x = acc.x / (1.f + expf(-acc.x));
    o.y = acc.y / (1.f + expf(-acc.y));
    o.z = acc.z / (1.f + expf(-acc.z));
    o.w = acc.w / (1.f + expf(-acc.w));
    *(float4*)&g_xconv[(size_t)t * DI + c] = o;
}

// ---------------- SSD stage A: head-dim 2-way split + liveness early-exit -------
__global__ __launch_bounds__(256)
void chunk_dstate_kernel()
{
    const int h = blockIdx.x;
    const int c = blockIdx.y;
    if (c == NC - 1) return;
    if (g_ephi[h*L + (c+1)*CT] == 0.f) return;

    const int z = blockIdx.z;
    const int t0 = c * CT;
    const int ib = z * 64;

    __shared__ float Bsh[CT][DS];
    __shared__ float Xsh[CT][64];

    const int tid = threadIdx.x;
    for (int idx = tid*4; idx < CT*DS; idx += 256*4) {
        int u = idx / DS, j = idx % DS;
        *(float4*)&Bsh[u][j] =
            *(const float4*)&g_proj[(size_t)(t0+u)*NPROJ + OFF_B + h*DS + j];
    }
    for (int idx = tid*4; idx < CT*64; idx += 256*4) {
        int u = idx / 64, i = idx % 64;
        float su = g_eneg[h*L + t0 + u] * g_dt[h*L + t0 + u];
        float4 xv = *(const float4*)&g_xconv[(size_t)(t0+u)*DI + h*HD + ib + i];
        xv.x *= su; xv.y *= su; xv.z *= su; xv.w *= su;
        *(float4*)&Xsh[u][i] = xv;
    }
    __syncthreads();

    const int lane = tid & 31;
    const int w    = tid >> 5;
    const int j0   = (w * 2 + (lane >> 4)) * 4;
    const int i0   = (lane & 15) * 4;

    float acc[4][4];
#pragma unroll
    for (int a = 0; a < 4; a++)
#pragma unroll
        for (int b = 0; b < 4; b++) acc[a][b] = 0.f;

    for (int u = 0; u < CT; u++) {
        float4 xv = *(const float4*)&Xsh[u][i0];
#pragma unroll
        for (int a = 0; a < 4; a++) {
            float bj = Bsh[u][j0 + a];
            acc[a][0] = fmaf(bj, xv.x, acc[a][0]);
            acc[a][1] = fmaf(bj, xv.y, acc[a][1]);
            acc[a][2] = fmaf(bj, xv.z, acc[a][2]);
            acc[a][3] = fmaf(bj, xv.w, acc[a][3]);
        }
    }
    float* dst = &g_dS[((size_t)(h*NC + c)) * DS * HD];
#pragma unroll
    for (int a = 0; a < 4; a++)
        *(float4*)&dst[(j0+a)*HD + ib + i0] = *(float4*)&acc[a][0];
}

// ---------------- SSD stage B: prefix with liveness break ------------------------
__global__ void state_prefix_kernel()
{
    int g = blockIdx.x * blockDim.x + threadIdx.x;
    if (g >= NH * DS * HD) return;
    int h = g / (DS*HD);
    int e = g % (DS*HD);
    float run = 0.f;
    for (int c = 0; c < NC; c++) {
        if (g_ephi[h*L + c*CT] == 0.f) break;
        size_t idx = ((size_t)(h*NC + c)) * DS * HD + e;
        g_S[idx] = run;
        run += g_dS[idx];
    }
}

// ---------------- SSD stage C: 2-way t-split + dead-block fast path -------------
__global__ __launch_bounds__(256)
void ssd_output_kernel(const float* __restrict__ Dp)
{
    const int h = blockIdx.x;
    const int c = blockIdx.y;
    const int z = blockIdx.z;
    const int t0 = c * CT;
    const int tz = z * 32;

    if (g_ephi[h*L + t0 + tz] == 0.f) {
        const int lane = threadIdx.x & 31;
        const int tg   = threadIdx.x >> 5;
        const int tb   = tg * 4;
        const int i0   = lane * 4;
        const int hbase = h * HD;
        const float dph = Dp[h];
#pragma unroll
        for (int s = 0; s < 4; s++) {
            int t = t0 + tz + tb + s;
            float4 xv = *(const float4*)&g_xconv[(size_t)t * DI + hbase + i0];
            float4 y = make_float4(dph * xv.x, dph * xv.y, dph * xv.z, dph * xv.w);
            *(float4*)&g_yssm[(size_t)t * DI + hbase + i0] = y;
        }
        return;
    }

    __shared__ float Csh [32][DSP];
    __shared__ float BGsh[CT][DSP];
    __shared__ float sphi[32], scoef[CT];

    const int tid = threadIdx.x;
    for (int idx = tid*4; idx < 32*DS; idx += 256*4) {
        int tl = idx / DS, j = idx % DS;
        *(float4*)&Csh[tl][j] =
            *(const float4*)&g_proj[(size_t)(t0+tz+tl)*NPROJ + OFF_C + h*DS + j];
    }
    for (int idx = tid*4; idx < CT*DS; idx += 256*4) {
        int u = idx / DS, j = idx % DS;
        *(float4*)&BGsh[u][j] =
            *(const float4*)&g_proj[(size_t)(t0+u)*NPROJ + OFF_B + h*DS + j];
    }
    if (tid < 32)
        sphi[tid] = g_ephi[h*L + t0 + tz + tid];
    if (tid < CT)
        scoef[tid] = g_eneg[h*L + t0 + tid] * g_dt[h*L + t0 + tid];
    __syncthreads();

    const int ulim = z ? CT : 32;

    {
        const int ut = tid & 15;
        const int tt = tid >> 4;
        const int ta = tt * 2;
        const int ua = ut * 4;
        float gacc[2][4];
#pragma unroll
        for (int a = 0; a < 2; a++)
#pragma unroll
            for (int b = 0; b < 4; b++) gacc[a][b] = 0.f;
        if (ua < ulim) {
            for (int k = 0; k < DS; k++) {
                float cr[2], br[4];
#pragma unroll
                for (int a = 0; a < 2; a++) cr[a] = Csh [ta+a][k];
#pragma unroll
                for (int b = 0; b < 4; b++) br[b] = BGsh[ua+b][k];
#pragma unroll
                for (int a = 0; a < 2; a++)
#pragma unroll
                    for (int b = 0; b < 4; b++)
                        gacc[a][b] = fmaf(cr[a], br[b], gacc[a][b]);
            }
        }
        __syncthreads();
#pragma unroll
        for (int a = 0; a < 2; a++)
#pragma unroll
            for (int b = 0; b < 4; b++) {
                int tl = ta + a, u = ua + b;
                float m = (tz + tl >= u) ? sphi[tl] * scoef[u] : 0.f;
                BGsh[tl][u] = m * gacc[a][b];
            }
        __syncthreads();
    }

    const int lane = tid & 31;
    const int tg   = tid >> 5;
    const int tb   = tg * 4;
    const int i0   = lane * 4;
    const int hbase = h * HD;
    const float dph = Dp[h];
    const float* Srow = &g_S[((size_t)(h*NC + c)) * DS * HD];

    float accI[4][4], accS[4][4];
#pragma unroll
    for (int s = 0; s < 4; s++)
#pragma unroll
        for (int b = 0; b < 4; b++) { accI[s][b] = 0.f; accS[s][b] = 0.f; }

    for (int u = 0; u < ulim; u++) {
        float4 xv = *(const float4*)&g_xconv[(size_t)(t0+u)*DI + hbase + i0];
#pragma unroll
        for (int s = 0; s < 4; s++) {
            float gv = BGsh[tb+s][u];
            accI[s][0] = fmaf(gv, xv.x, accI[s][0]);
            accI[s][1] = fmaf(gv, xv.y, accI[s][1]);
            accI[s][2] = fmaf(gv, xv.z, accI[s][2]);
            accI[s][3] = fmaf(gv, xv.w, accI[s][3]);
        }
    }
    for (int j = 0; j < DS; j++) {
        float4 sv = *(const float4*)&Srow[j*HD + i0];
#pragma unroll
        for (int s = 0; s < 4; s++) {
            float cj = Csh[tb+s][j];
            accS[s][0] = fmaf(cj, sv.x, accS[s][0]);
            accS[s][1] = fmaf(cj, sv.y, accS[s][1]);
            accS[s][2] = fmaf(cj, sv.z, accS[s][2]);
            accS[s][3] = fmaf(cj, sv.w, accS[s][3]);
        }
    }
#pragma unroll
    for (int s = 0; s < 4; s++) {
        int t = t0 + tz + tb + s;
        float p = sphi[tb + s];
        float4 xv = *(const float4*)&g_xconv[(size_t)t * DI + hbase + i0];
        float4 y;
        y.x = fmaf(p, accS[s][0], accI[s][0]) + dph * xv.x;
        y.y = fmaf(p, accS[s][1], accI[s][1]) + dph * xv.y;
        y.z = fmaf(p, accS[s][2], accI[s][2]) + dph * xv.z;
        y.w = fmaf(p, accS[s][3], accI[s][3]) + dph * xv.w;
        *(float4*)&g_yssm[(size_t)t * DI + hbase + i0] = y;
    }
}

// ---------------- RMS norm + gate + bf16 split (vectorized) ---------------------
__global__ void rms_gate_kernel(const float* __restrict__ norm_w)
{
    const int t = blockIdx.x;
    __shared__ float red[256];
    float s = 0.f;
    for (int idx = threadIdx.x; idx < DI/4; idx += 256) {
        float4 v = *(const float4*)&g_yssm[(size_t)t * DI + idx*4];
        s = fmaf(v.x, v.x, s); s = fmaf(v.y, v.y, s);
        s = fmaf(v.z, v.z, s); s = fmaf(v.w, v.w, s);
    }
    red[threadIdx.x] = s;
    __syncthreads();
    for (int o = 128; o > 0; o >>= 1) {
        if (threadIdx.x < o) red[threadIdx.x] += red[threadIdx.x + o];
        __syncthreads();
    }
    float rms = rsqrtf(red[0] / (float)DI + 1e-5f);
    for (int idx = threadIdx.x; idx < DI/4; idx += 256) {
        const int c = idx * 4;
        float4 v  = *(const float4*)&g_yssm[(size_t)t * DI + c];
        float4 z4 = *(const float4*)&g_proj[(size_t)t * NPROJ + c];
        float4 w4 = *(const float4*)&norm_w[c];
        float yb[4];
        yb[0] = v.x * rms * w4.x * (z4.x / (1.f + expf(-z4.x)));
        yb[1] = v.y * rms * w4.y * (z4.y / (1.f + expf(-z4.y)));
        yb[2] = v.z * rms * w4.z * (z4.z / (1.f + expf(-z4.z)));
        yb[3] = v.w * rms * w4.w * (z4.w / (1.f + expf(-z4.w)));
        __nv_bfloat16 h[4];
        float l[4];
#pragma unroll
        for (int k = 0; k < 4; k++) {
            h[k] = __float2bfloat16(yb[k]);
            l[k] = yb[k] - __bfloat162float(h[k]);
        }
        uint2 hv, lv;
        hv.x = pack_bf2(__bfloat162float(h[0]), __bfloat162float(h[1]));
        hv.y = pack_bf2(__bfloat162float(h[2]), __bfloat162float(h[3]));
        lv.x = pack_bf2(l[0], l[1]);
        lv.y = pack_bf2(l[2], l[3]);
        *(uint2*)&g_yh[(size_t)t * DI + c] = hv;
        *(uint2*)&g_yl[(size_t)t * DI + c] = lv;
    }
}

// ---------------- launch --------------------------------------------------------
extern "C" void kernel_launch(void* const* d_in, const int* in_sizes, int n_in,
                              void* d_out, int out_size)
{
    const float* x       = (const float*)d_in[0];
    const float* W_in    = (const float*)d_in[1];
    const float* conv_w  = (const float*)d_in[2];
    const float* conv_b  = (const float*)d_in[3];
    const float* A_log   = (const float*)d_in[4];
    const float* Dp      = (const float*)d_in[5];
    const float* dt_bias = (const float*)d_in[6];
    const float* W_out   = (const float*)d_in[7];
    const float* norm_w  = (const float*)d_in[8];
    float* out = (float*)d_out;

    float *proj_p, *outp_p, *ephi_p;
    __nv_bfloat16 *xh, *xl, *w1h, *w1l, *yh, *yl, *w2h, *w2l;
    cudaGetSymbolAddress((void**)&proj_p, g_proj);
    cudaGetSymbolAddress((void**)&outp_p, g_out_p);
    cudaGetSymbolAddress((void**)&ephi_p, g_ephi);
    cudaGetSymbolAddress((void**)&xh,  g_xh);  cudaGetSymbolAddress((void**)&xl,  g_xl);
    cudaGetSymbolAddress((void**)&w1h, g_w1h); cudaGetSymbolAddress((void**)&w1l, g_w1l);
    cudaGetSymbolAddress((void**)&yh,  g_yh);  cudaGetSymbolAddress((void**)&yl,  g_yl);
    cudaGetSymbolAddress((void**)&w2h, g_w2h); cudaGetSymbolAddress((void**)&w2l, g_w2l);

    cudaFuncSetAttribute(bf16_gemm_nt, cudaFuncAttributeMaxDynamicSharedMemorySize, GEMM_SMEM);

    // 0a) dt GEMV (x read once) + Phi scan — cheap, feeds GEMM1 liveness
    dt_gemv_kernel<<<L/64, 256>>>(x, W_in);
    dt_phi_kernel<<<NH, 256>>>(A_log, dt_bias);

    // 0b) fused bf16 hi/lo splits
    split3_kernel<<<(NTOT/8 + 255)/256, 256>>>(x, W_in, W_out);

    // 1) proj = x @ W_in^T — 64-row tiles, 2 CTAs/SM, dead-tile skip
    bf16_gemm_nt<<<dim3((NPROJ + 127)/128, L/64, 1), 256, GEMM_SMEM>>>(
        L, NPROJ, DM, DM, xh, xl, w1h, w1l, proj_p, ephi_p);

    // 2) conv + silu
    conv_silu_kernel<<<CONVBLKS, 256>>>(conv_w, conv_b);

    // 3) SSD pipeline with liveness early-exits
    chunk_dstate_kernel<<<dim3(NH, NC, 2), 256>>>();
    state_prefix_kernel<<<(NH*DS*HD + 255)/256, 256>>>();
    ssd_output_kernel<<<dim3(NH, NC, 2), 256>>>(Dp);

    // 4) RMS norm + gate + split
    rms_gate_kernel<<<L, 256>>>(norm_w);

    // 5) out = ybar @ W_out^T, split-K=3 + combine
    bf16_gemm_nt<<<dim3(DM/128, L/64, KSPLIT), 256, GEMM_SMEM>>>(
        L, DM, DI/KSPLIT, DI, yh, yl, w2h, w2l, outp_p, nullptr);
    combine_kernel<<<(L*DM + 255)/256, 256>>>(out);
}

// round 17
// speedup vs baseline: 1.3073x; 1.1467x over previous
#include <cuda_runtime.h>
#include <cuda_bf16.h>
#include <math.h>
#include <stdint.h>

#define L      1024
#define DM     768
#define DI     1536
#define NH     12
#define HD     128
#define DS     64
#define NPROJ  4620
#define OFF_X  1536
#define OFF_B  3072
#define OFF_C  3840
#define OFF_DT 4608
#define NC     16
#define CT     64
#define DSP    (DS + 4)
#define KSPLIT 3

// ---------------- scratch -------------------------------------------------------
__device__ float g_proj [L * NPROJ];
__device__ float g_xconv[L * DI];
__device__ float g_dtraw[NH * L];
__device__ float g_dt   [NH * L];
__device__ float g_eneg [NH * L];
__device__ float g_ephi [NH * L];
__device__ float g_yssm [L * DI];
__device__ float g_dS   [NH * NC * DS * HD];
__device__ float g_S    [NH * NC * DS * HD];
__device__ float g_out_p[KSPLIT * L * DM];
__device__ __nv_bfloat16 g_xh [L * DM],    g_xl [L * DM];
__device__ __nv_bfloat16 g_w1h[NPROJ*DM],  g_w1l[NPROJ*DM];
__device__ __nv_bfloat16 g_yh [L * DI],    g_yl [L * DI];
__device__ __nv_bfloat16 g_w2h[DM * DI],   g_w2l[DM * DI];

// ---------------- helpers -------------------------------------------------------
__device__ __forceinline__ uint32_t smem_u32(const void* p) {
    uint32_t a;
    asm("{ .reg .u64 t; cvta.to.shared.u64 t, %1; cvt.u32.u64 %0, t; }" : "=r"(a) : "l"(p));
    return a;
}
__device__ __forceinline__ void cp16(uint32_t dst, const void* src) {
    asm volatile("cp.async.cg.shared.global [%0], [%1], 16;" :: "r"(dst), "l"(src));
}
#define CP_COMMIT() asm volatile("cp.async.commit_group;" ::: "memory")
#define CP_WAIT(n)  asm volatile("cp.async.wait_group %0;" :: "n"(n) : "memory")

__device__ __forceinline__ void mma_bf16(float* d, const uint32_t* a,
                                         uint32_t b0, uint32_t b1) {
    asm volatile(
        "mma.sync.aligned.m16n8k16.row.col.f32.bf16.bf16.f32 "
        "{%0,%1,%2,%3},{%4,%5,%6,%7},{%8,%9},{%0,%1,%2,%3};"
        : "+f"(d[0]), "+f"(d[1]), "+f"(d[2]), "+f"(d[3])
        : "r"(a[0]), "r"(a[1]), "r"(a[2]), "r"(a[3]), "r"(b0), "r"(b1));
}
__device__ __forceinline__ void ldsm4(uint32_t* r, uint32_t addr) {
    asm volatile("ldmatrix.sync.aligned.m8n8.x4.shared.b16 {%0,%1,%2,%3}, [%4];"
                 : "=r"(r[0]), "=r"(r[1]), "=r"(r[2]), "=r"(r[3]) : "r"(addr));
}
__device__ __forceinline__ uint32_t pack_bf2(float a, float b) {
    __nv_bfloat162 v = __floats2bfloat162_rn(a, b);
    return *(uint32_t*)&v;
}

// ---------------- fused: split3 (vectorized) + dt GEMV tail blocks --------------
#define NS1 (L*DM)
#define NS2 (NPROJ*DM)
#define NS3 (DM*DI)
#define NTOT (NS1+NS2+NS3)
#define SPLITBLKS ((NTOT/8 + 255) / 256)     // 2693
#define GEMVBLKS  (L / 8)                    // 128

__global__ __launch_bounds__(256)
void split_gemv_kernel(const float* __restrict__ x,
                       const float* __restrict__ W_in,
                       const float* __restrict__ W_out)
{
    __shared__ float wsm[NH][DM];            // used by GEMV path only (36 KB)

    if (blockIdx.x < SPLITBLKS) {
        long i = ((long)blockIdx.x * 256 + threadIdx.x) * 8;
        if (i >= NTOT) return;
        const float* src; __nv_bfloat16 *hi, *lo; long j;
        if (i < NS1)          { src = x;     hi = g_xh;  lo = g_xl;  j = i; }
        else if (i < NS1+NS2) { src = W_in;  hi = g_w1h; lo = g_w1l; j = i - NS1; }
        else                  { src = W_out; hi = g_w2h; lo = g_w2l; j = i - NS1 - NS2; }
        float4 a = *(const float4*)&src[j];
        float4 b = *(const float4*)&src[j + 4];
        float v[8] = {a.x, a.y, a.z, a.w, b.x, b.y, b.z, b.w};
        __nv_bfloat16 h[8];
        float l[8];
#pragma unroll
        for (int k = 0; k < 8; k++) {
            h[k] = __float2bfloat16(v[k]);
            l[k] = v[k] - __bfloat162float(h[k]);
        }
        uint4 hv, lv;
        hv.x = pack_bf2(__bfloat162float(h[0]), __bfloat162float(h[1]));
        hv.y = pack_bf2(__bfloat162float(h[2]), __bfloat162float(h[3]));
        hv.z = pack_bf2(__bfloat162float(h[4]), __bfloat162float(h[5]));
        hv.w = pack_bf2(__bfloat162float(h[6]), __bfloat162float(h[7]));
        lv.x = pack_bf2(l[0], l[1]);
        lv.y = pack_bf2(l[2], l[3]);
        lv.z = pack_bf2(l[4], l[5]);
        lv.w = pack_bf2(l[6], l[7]);
        *(uint4*)&hi[j] = hv;
        *(uint4*)&lo[j] = lv;
    } else {
        // dt GEMV: 128 blocks x 8 warps, one warp per timestep.
        for (int k = threadIdx.x; k < NH * DM; k += 256)
            wsm[k / DM][k % DM] = W_in[(size_t)OFF_DT * DM + k];
        __syncthreads();

        const int w = threadIdx.x >> 5, lane = threadIdx.x & 31;
        const int t = (blockIdx.x - SPLITBLKS) * 8 + w;
        float4 xr[6];
#pragma unroll
        for (int j = 0; j < 6; j++)
            xr[j] = *(const float4*)&x[(size_t)t * DM + lane * 4 + j * 128];
#pragma unroll
        for (int h = 0; h < NH; h++) {
            float s = 0.f;
#pragma unroll
            for (int j = 0; j < 6; j++) {
                float4 wv = *(const float4*)&wsm[h][lane * 4 + j * 128];
                s = fmaf(xr[j].x, wv.x, fmaf(xr[j].y, wv.y,
                    fmaf(xr[j].z, wv.z, fmaf(xr[j].w, wv.w, s))));
            }
#pragma unroll
            for (int o = 16; o > 0; o >>= 1)
                s += __shfl_xor_sync(0xffffffffu, s, o);
            if (lane == 0) g_dtraw[h*L + t] = s;
        }
    }
}

// ---------------- dt / Phi scan (block per head) ---------------------------------
__global__ __launch_bounds__(256)
void dt_phi_kernel(const float* __restrict__ A_log,
                   const float* __restrict__ dt_bias)
{
    const int h   = blockIdx.x;
    const int tid = threadIdx.x;
    const int lane = tid & 31;
    const int w    = tid >> 5;
    const float Ah   = -expf(A_log[h]);
    const float bias = dt_bias[h];
    __shared__ float wsum[8];

    const int t0 = tid * 4;
    float dt[4];
    float loc = 0.f;
#pragma unroll
    for (int i = 0; i < 4; i++) {
        float xr = g_dtraw[h*L + t0 + i];
        dt[i] = fmaxf(xr, 0.f) + log1pf(expf(-fabsf(xr))) + bias;
        g_dt[h*L + t0 + i] = dt[i];
        loc += Ah * dt[i];
    }
    float s = loc;
#pragma unroll
    for (int o = 1; o < 32; o <<= 1) {
        float v = __shfl_up_sync(0xffffffffu, s, o);
        if (lane >= o) s += v;
    }
    if (lane == 31) wsum[w] = s;
    __syncthreads();
    float wexcl = 0.f;
#pragma unroll
    for (int i = 0; i < 7; i++)
        if (i < w) wexcl += wsum[i];
    float run = wexcl + (s - loc);
#pragma unroll
    for (int i = 0; i < 4; i++) {
        run += Ah * dt[i];
        g_eneg[h*L + t0 + i] = expf(fminf(-run, 80.f));
        g_ephi[h*L + t0 + i] = expf(run);
    }
}

// ---------------- bf16 3-term mma GEMM: 64x128 tiles, 2 CTAs/SM, liveness skip --
#define GSTRIDE_B 80
#define BMR       64
#define ARR_A_B   (BMR * GSTRIDE_B)          // 5120
#define ARR_B_B   (128 * GSTRIDE_B)          // 10240
#define STAGE_B   (2*ARR_A_B + 2*ARR_B_B)    // 30720
#define OFF_AH    0
#define OFF_AL    ARR_A_B
#define OFF_BH    (2*ARR_A_B)
#define OFF_BL    (2*ARR_A_B + ARR_B_B)
#define GEMM_SMEM (3 * STAGE_B)              // 92160

__global__ __launch_bounds__(256, 2)
void bf16_gemm_nt(int M, int N, int K, int ldk,
                  const __nv_bfloat16* __restrict__ Ahi, const __nv_bfloat16* __restrict__ Alo,
                  const __nv_bfloat16* __restrict__ Bhi, const __nv_bfloat16* __restrict__ Blo,
                  float* __restrict__ C, const float* __restrict__ live)
{
    const long m0 = (long)blockIdx.y * BMR;
    const long n0 = (long)blockIdx.x * 128;

    // Liveness skip (GEMM1): x-tiles 24..35 are pure B/C columns for 2 heads;
    // dead iff ephi[h*L+m0]==0 for both (ephi decreasing in t).
    // x-tile 36 is dt columns only — dt comes from the GEMV path, never read.
    if (live) {
        const int bx = blockIdx.x;
        if (bx >= 24) {
            if (bx >= 36) return;
            const int r  = bx - 24;
            const int hh = (r < 6) ? 2*r : 2*(r - 6);
            if (live[hh*L + m0] == 0.f && live[(hh+1)*L + m0] == 0.f) return;
        }
    }

    const long koff = (long)blockIdx.z * K;
    Ahi += koff; Alo += koff; Bhi += koff; Blo += koff;
    C   += (long)blockIdx.z * M * N;

    extern __shared__ char smem[];
    const uint32_t sb = smem_u32(smem);

    const int tid    = threadIdx.x;
    const int lane   = tid & 31;
    const int wid    = tid >> 5;
    const int g      = lane >> 2;
    const int tg     = lane & 3;
    const int lr     = lane & 7;
    const int q      = lane >> 3;
    const int warp_m = wid >> 2;
    const int warp_n = wid & 3;

    uint32_t aoff[2][2];
#pragma unroll
    for (int ma = 0; ma < 2; ma++) {
        const int rr = warp_m * 32 + ma * 16;
#pragma unroll
        for (int ka = 0; ka < 2; ka++)
            aoff[ma][ka] = (uint32_t)((rr + lr + (q & 1) * 8) * GSTRIDE_B + ka * 32 + (q >> 1) * 16);
    }
    uint32_t boff[2][2];
#pragma unroll
    for (int na2 = 0; na2 < 2; na2++) {
        const int cc = warp_n * 32 + na2 * 16;
#pragma unroll
        for (int ka = 0; ka < 2; ka++)
            boff[na2][ka] = (uint32_t)((cc + lr + (q >> 1) * 8) * GSTRIDE_B + ka * 32 + (q & 1) * 16);
    }

    const int nchunk = K >> 5;

    float d[2][4][4];
#pragma unroll
    for (int i = 0; i < 2; i++)
#pragma unroll
        for (int j = 0; j < 4; j++)
#pragma unroll
            for (int r = 0; r < 4; r++) d[i][j][r] = 0.f;

    auto issue_stage = [&](int kc) {
        const int k0 = kc << 5;
        const uint32_t base = sb + (kc % 3) * STAGE_B;
        {
            const int r = tid >> 2, col = (tid & 3) * 8;
            cp16(base + OFF_AH + r*GSTRIDE_B + col*2, &Ahi[(m0 + r) * ldk + k0 + col]);
            cp16(base + OFF_AL + r*GSTRIDE_B + col*2, &Alo[(m0 + r) * ldk + k0 + col]);
        }
#pragma unroll
        for (int c = tid; c < 512; c += 256) {
            const int r = c >> 2, col = (c & 3) * 8;
            const long nr = (n0 + r < N) ? (n0 + r) : (N - 1);
            cp16(base + OFF_BH + r*GSTRIDE_B + col*2, &Bhi[nr * ldk + k0 + col]);
            cp16(base + OFF_BL + r*GSTRIDE_B + col*2, &Blo[nr * ldk + k0 + col]);
        }
        CP_COMMIT();
    };

    issue_stage(0);
    if (nchunk > 1) issue_stage(1);

    for (int kc = 0; kc < nchunk; kc++) {
        __syncthreads();
        if (kc + 2 < nchunk) { issue_stage(kc + 2); CP_WAIT(2); }
        else if (kc + 1 < nchunk) { CP_WAIT(1); }
        else { CP_WAIT(0); }
        __syncthreads();

        const uint32_t st  = sb + (kc % 3) * STAGE_B;
        const uint32_t pAh = st + OFF_AH;
        const uint32_t pAl = st + OFF_AL;
        const uint32_t pBh = st + OFF_BH;
        const uint32_t pBl = st + OFF_BL;

#pragma unroll
        for (int ka = 0; ka < 2; ka++) {
            uint32_t ah[2][4], al[2][4];
#pragma unroll
            for (int ma = 0; ma < 2; ma++) {
                ldsm4(ah[ma], pAh + aoff[ma][ka]);
                ldsm4(al[ma], pAl + aoff[ma][ka]);
            }
            uint32_t bh[4][2], bl[4][2];
#pragma unroll
            for (int na2 = 0; na2 < 2; na2++) {
                uint32_t th[4], tl[4];
                ldsm4(th, pBh + boff[na2][ka]);
                ldsm4(tl, pBl + boff[na2][ka]);
                bh[na2*2][0] = th[0]; bh[na2*2][1] = th[1];
                bh[na2*2+1][0] = th[2]; bh[na2*2+1][1] = th[3];
                bl[na2*2][0] = tl[0]; bl[na2*2][1] = tl[1];
                bl[na2*2+1][0] = tl[2]; bl[na2*2+1][1] = tl[3];
            }
#pragma unroll
            for (int na = 0; na < 4; na++)
#pragma unroll
                for (int ma = 0; ma < 2; ma++)
                    mma_bf16(d[ma][na], ah[ma], bh[na][0], bh[na][1]);
#pragma unroll
            for (int na = 0; na < 4; na++)
#pragma unroll
                for (int ma = 0; ma < 2; ma++)
                    mma_bf16(d[ma][na], al[ma], bh[na][0], bh[na][1]);
#pragma unroll
            for (int na = 0; na < 4; na++)
#pragma unroll
                for (int ma = 0; ma < 2; ma++)
                    mma_bf16(d[ma][na], ah[ma], bl[na][0], bl[na][1]);
        }
    }

#pragma unroll
    for (int ma = 0; ma < 2; ma++) {
        const long rbase = m0 + warp_m * 32 + ma * 16;
#pragma unroll
        for (int na = 0; na < 4; na++) {
            const long col = n0 + warp_n * 32 + na * 8 + 2 * tg;
            if (col < N) {
                *(float2*)&C[(rbase + g    ) * N + col] = make_float2(d[ma][na][0], d[ma][na][1]);
                *(float2*)&C[(rbase + g + 8) * N + col] = make_float2(d[ma][na][2], d[ma][na][3]);
            }
        }
    }
}

// ---------------- split-K combine -----------------------------------------------
__global__ void combine_kernel(float* __restrict__ out)
{
    int i = blockIdx.x * blockDim.x + threadIdx.x;
    if (i < L * DM)
        out[i] = (g_out_p[i] + g_out_p[i + L*DM]) + g_out_p[i + 2*L*DM];
}

// ---------------- conv1d+silu (vectorized) --------------------------------------
#define CONVBLKS (L * (DI/4) / 256)          // 1536
__global__ __launch_bounds__(256)
void conv_silu_kernel(const float* __restrict__ conv_w,
                      const float* __restrict__ conv_b)
{
    int id = blockIdx.x * 256 + threadIdx.x;
    int t = id / (DI/4);
    int c = (id % (DI/4)) * 4;
    float4 acc = *(const float4*)&conv_b[c];
#pragma unroll
    for (int i = 0; i < 4; i++) {
        int ts = t + i - 3;
        if (ts >= 0) {
            float4 xv = *(const float4*)&g_proj[(size_t)ts * NPROJ + OFF_X + c];
            acc.x = fmaf(xv.x, conv_w[(c+0)*4 + i], acc.x);
            acc.y = fmaf(xv.y, conv_w[(c+1)*4 + i], acc.y);
            acc.z = fmaf(xv.z, conv_w[(c+2)*4 + i], acc.z);
            acc.w = fmaf(xv.w, conv_w[(c+3)*4 + i], acc.w);
        }
    }
    float4 o;
    o.x = acc.x / (1.f + expf(-acc.x));
    o.y = acc.y / (1.f + expf(-acc.y));
    o.z = acc.z / (1.f + expf(-acc.z));
    o.w = acc.w / (1.f + expf(-acc.w));
    *(float4*)&g_xconv[(size_t)t * DI + c] = o;
}

// ---------------- SSD stage A: head-dim 2-way split + liveness early-exit -------
__global__ __launch_bounds__(256)
void chunk_dstate_kernel()
{
    const int h = blockIdx.x;
    const int c = blockIdx.y;
    if (c == NC - 1) return;
    if (g_ephi[h*L + (c+1)*CT] == 0.f) return;

    const int z = blockIdx.z;
    const int t0 = c * CT;
    const int ib = z * 64;

    __shared__ float Bsh[CT][DS];
    __shared__ float Xsh[CT][64];

    const int tid = threadIdx.x;
    for (int idx = tid*4; idx < CT*DS; idx += 256*4) {
        int u = idx / DS, j = idx % DS;
        *(float4*)&Bsh[u][j] =
            *(const float4*)&g_proj[(size_t)(t0+u)*NPROJ + OFF_B + h*DS + j];
    }
    for (int idx = tid*4; idx < CT*64; idx += 256*4) {
        int u = idx / 64, i = idx % 64;
        float su = g_eneg[h*L + t0 + u] * g_dt[h*L + t0 + u];
        float4 xv = *(const float4*)&g_xconv[(size_t)(t0+u)*DI + h*HD + ib + i];
        xv.x *= su; xv.y *= su; xv.z *= su; xv.w *= su;
        *(float4*)&Xsh[u][i] = xv;
    }
    __syncthreads();

    const int lane = tid & 31;
    const int w    = tid >> 5;
    const int j0   = (w * 2 + (lane >> 4)) * 4;
    const int i0   = (lane & 15) * 4;

    float acc[4][4];
#pragma unroll
    for (int a = 0; a < 4; a++)
#pragma unroll
        for (int b = 0; b < 4; b++) acc[a][b] = 0.f;

    for (int u = 0; u < CT; u++) {
        float4 xv = *(const float4*)&Xsh[u][i0];
#pragma unroll
        for (int a = 0; a < 4; a++) {
            float bj = Bsh[u][j0 + a];
            acc[a][0] = fmaf(bj, xv.x, acc[a][0]);
            acc[a][1] = fmaf(bj, xv.y, acc[a][1]);
            acc[a][2] = fmaf(bj, xv.z, acc[a][2]);
            acc[a][3] = fmaf(bj, xv.w, acc[a][3]);
        }
    }
    float* dst = &g_dS[((size_t)(h*NC + c)) * DS * HD];
#pragma unroll
    for (int a = 0; a < 4; a++)
        *(float4*)&dst[(j0+a)*HD + ib + i0] = *(float4*)&acc[a][0];
}

// ---------------- SSD stage B: prefix with liveness break ------------------------
__global__ void state_prefix_kernel()
{
    int g = blockIdx.x * blockDim.x + threadIdx.x;
    if (g >= NH * DS * HD) return;
    int h = g / (DS*HD);
    int e = g % (DS*HD);
    float run = 0.f;
    for (int c = 0; c < NC; c++) {
        if (g_ephi[h*L + c*CT] == 0.f) break;
        size_t idx = ((size_t)(h*NC + c)) * DS * HD + e;
        g_S[idx] = run;
        run += g_dS[idx];
    }
}

// ---------------- SSD stage C: 2-way t-split + dead-block fast path -------------
__global__ __launch_bounds__(256)
void ssd_output_kernel(const float* __restrict__ Dp)
{
    const int h = blockIdx.x;
    const int c = blockIdx.y;
    const int z = blockIdx.z;
    const int t0 = c * CT;
    const int tz = z * 32;

    if (g_ephi[h*L + t0 + tz] == 0.f) {
        const int lane = threadIdx.x & 31;
        const int tg   = threadIdx.x >> 5;
        const int tb   = tg * 4;
        const int i0   = lane * 4;
        const int hbase = h * HD;
        const float dph = Dp[h];
#pragma unroll
        for (int s = 0; s < 4; s++) {
            int t = t0 + tz + tb + s;
            float4 xv = *(const float4*)&g_xconv[(size_t)t * DI + hbase + i0];
            float4 y = make_float4(dph * xv.x, dph * xv.y, dph * xv.z, dph * xv.w);
            *(float4*)&g_yssm[(size_t)t * DI + hbase + i0] = y;
        }
        return;
    }

    __shared__ float Csh [32][DSP];
    __shared__ float BGsh[CT][DSP];
    __shared__ float sphi[32], scoef[CT];

    const int tid = threadIdx.x;
    for (int idx = tid*4; idx < 32*DS; idx += 256*4) {
        int tl = idx / DS, j = idx % DS;
        *(float4*)&Csh[tl][j] =
            *(const float4*)&g_proj[(size_t)(t0+tz+tl)*NPROJ + OFF_C + h*DS + j];
    }
    for (int idx = tid*4; idx < CT*DS; idx += 256*4) {
        int u = idx / DS, j = idx % DS;
        *(float4*)&BGsh[u][j] =
            *(const float4*)&g_proj[(size_t)(t0+u)*NPROJ + OFF_B + h*DS + j];
    }
    if (tid < 32)
        sphi[tid] = g_ephi[h*L + t0 + tz + tid];
    if (tid < CT)
        scoef[tid] = g_eneg[h*L + t0 + tid] * g_dt[h*L + t0 + tid];
    __syncthreads();

    const int ulim = z ? CT : 32;

    {
        const int ut = tid & 15;
        const int tt = tid >> 4;
        const int ta = tt * 2;
        const int ua = ut * 4;
        float gacc[2][4];
#pragma unroll
        for (int a = 0; a < 2; a++)
#pragma unroll
            for (int b = 0; b < 4; b++) gacc[a][b] = 0.f;
        if (ua < ulim) {
            for (int k = 0; k < DS; k++) {
                float cr[2], br[4];
#pragma unroll
                for (int a = 0; a < 2; a++) cr[a] = Csh [ta+a][k];
#pragma unroll
                for (int b = 0; b < 4; b++) br[b] = BGsh[ua+b][k];
#pragma unroll
                for (int a = 0; a < 2; a++)
#pragma unroll
                    for (int b = 0; b < 4; b++)
                        gacc[a][b] = fmaf(cr[a], br[b], gacc[a][b]);
            }
        }
        __syncthreads();
#pragma unroll
        for (int a = 0; a < 2; a++)
#pragma unroll
            for (int b = 0; b < 4; b++) {
                int tl = ta + a, u = ua + b;
                float m = (tz + tl >= u) ? sphi[tl] * scoef[u] : 0.f;
                BGsh[tl][u] = m * gacc[a][b];
            }
        __syncthreads();
    }

    const int lane = tid & 31;
    const int tg   = tid >> 5;
    const int tb   = tg * 4;
    const int i0   = lane * 4;
    const int hbase = h * HD;
    const float dph = Dp[h];
    const float* Srow = &g_S[((size_t)(h*NC + c)) * DS * HD];

    float accI[4][4], accS[4][4];
#pragma unroll
    for (int s = 0; s < 4; s++)
#pragma unroll
        for (int b = 0; b < 4; b++) { accI[s][b] = 0.f; accS[s][b] = 0.f; }

    for (int u = 0; u < ulim; u++) {
        float4 xv = *(const float4*)&g_xconv[(size_t)(t0+u)*DI + hbase + i0];
#pragma unroll
        for (int s = 0; s < 4; s++) {
            float gv = BGsh[tb+s][u];
            accI[s][0] = fmaf(gv, xv.x, accI[s][0]);
            accI[s][1] = fmaf(gv, xv.y, accI[s][1]);
            accI[s][2] = fmaf(gv, xv.z, accI[s][2]);
            accI[s][3] = fmaf(gv, xv.w, accI[s][3]);
        }
    }
    for (int j = 0; j < DS; j++) {
        float4 sv = *(const float4*)&Srow[j*HD + i0];
#pragma unroll
        for (int s = 0; s < 4; s++) {
            float cj = Csh[tb+s][j];
            accS[s][0] = fmaf(cj, sv.x, accS[s][0]);
            accS[s][1] = fmaf(cj, sv.y, accS[s][1]);
            accS[s][2] = fmaf(cj, sv.z, accS[s][2]);
            accS[s][3] = fmaf(cj, sv.w, accS[s][3]);
        }
    }
#pragma unroll
    for (int s = 0; s < 4; s++) {
        int t = t0 + tz + tb + s;
        float p = sphi[tb + s];
        float4 xv = *(const float4*)&g_xconv[(size_t)t * DI + hbase + i0];
        float4 y;
        y.x = fmaf(p, accS[s][0], accI[s][0]) + dph * xv.x;
        y.y = fmaf(p, accS[s][1], accI[s][1]) + dph * xv.y;
        y.z = fmaf(p, accS[s][2], accI[s][2]) + dph * xv.z;
        y.w = fmaf(p, accS[s][3], accI[s][3]) + dph * xv.w;
        *(float4*)&g_yssm[(size_t)t * DI + hbase + i0] = y;
    }
}

// ---------------- RMS norm + gate + bf16 split (vectorized) ---------------------
__global__ void rms_gate_kernel(const float* __restrict__ norm_w)
{
    const int t = blockIdx.x;
    __shared__ float red[256];
    float s = 0.f;
    for (int idx = threadIdx.x; idx < DI/4; idx += 256) {
        float4 v = *(const float4*)&g_yssm[(size_t)t * DI + idx*4];
        s = fmaf(v.x, v.x, s); s = fmaf(v.y, v.y, s);
        s = fmaf(v.z, v.z, s); s = fmaf(v.w, v.w, s);
    }
    red[threadIdx.x] = s;
    __syncthreads();
    for (int o = 128; o > 0; o >>= 1) {
        if (threadIdx.x < o) red[threadIdx.x] += red[threadIdx.x + o];
        __syncthreads();
    }
    float rms = rsqrtf(red[0] / (float)DI + 1e-5f);
    for (int idx = threadIdx.x; idx < DI/4; idx += 256) {
        const int c = idx * 4;
        float4 v  = *(const float4*)&g_yssm[(size_t)t * DI + c];
        float4 z4 = *(const float4*)&g_proj[(size_t)t * NPROJ + c];
        float4 w4 = *(const float4*)&norm_w[c];
        float yb[4];
        yb[0] = v.x * rms * w4.x * (z4.x / (1.f + expf(-z4.x)));
        yb[1] = v.y * rms * w4.y * (z4.y / (1.f + expf(-z4.y)));
        yb[2] = v.z * rms * w4.z * (z4.z / (1.f + expf(-z4.z)));
        yb[3] = v.w * rms * w4.w * (z4.w / (1.f + expf(-z4.w)));
        __nv_bfloat16 h[4];
        float l[4];
#pragma unroll
        for (int k = 0; k < 4; k++) {
            h[k] = __float2bfloat16(yb[k]);
            l[k] = yb[k] - __bfloat162float(h[k]);
        }
        uint2 hv, lv;
        hv.x = pack_bf2(__bfloat162float(h[0]), __bfloat162float(h[1]));
        hv.y = pack_bf2(__bfloat162float(h[2]), __bfloat162float(h[3]));
        lv.x = pack_bf2(l[0], l[1]);
        lv.y = pack_bf2(l[2], l[3]);
        *(uint2*)&g_yh[(size_t)t * DI + c] = hv;
        *(uint2*)&g_yl[(size_t)t * DI + c] = lv;
    }
}

// ---------------- launch --------------------------------------------------------
extern "C" void kernel_launch(void* const* d_in, const int* in_sizes, int n_in,
                              void* d_out, int out_size)
{
    const float* x       = (const float*)d_in[0];
    const float* W_in    = (const float*)d_in[1];
    const float* conv_w  = (const float*)d_in[2];
    const float* conv_b  = (const float*)d_in[3];
    const float* A_log   = (const float*)d_in[4];
    const float* Dp      = (const float*)d_in[5];
    const float* dt_bias = (const float*)d_in[6];
    const float* W_out   = (const float*)d_in[7];
    const float* norm_w  = (const float*)d_in[8];
    float* out = (float*)d_out;

    float *proj_p, *outp_p, *ephi_p;
    __nv_bfloat16 *xh, *xl, *w1h, *w1l, *yh, *yl, *w2h, *w2l;
    cudaGetSymbolAddress((void**)&proj_p, g_proj);
    cudaGetSymbolAddress((void**)&outp_p, g_out_p);
    cudaGetSymbolAddress((void**)&ephi_p, g_ephi);
    cudaGetSymbolAddress((void**)&xh,  g_xh);  cudaGetSymbolAddress((void**)&xl,  g_xl);
    cudaGetSymbolAddress((void**)&w1h, g_w1h); cudaGetSymbolAddress((void**)&w1l, g_w1l);
    cudaGetSymbolAddress((void**)&yh,  g_yh);  cudaGetSymbolAddress((void**)&yl,  g_yl);
    cudaGetSymbolAddress((void**)&w2h, g_w2h); cudaGetSymbolAddress((void**)&w2l, g_w2l);

    cudaFuncSetAttribute(bf16_gemm_nt, cudaFuncAttributeMaxDynamicSharedMemorySize, GEMM_SMEM);

    // 0) fused: bf16 splits + dt GEMV (128 parallel tail blocks)
    split_gemv_kernel<<<SPLITBLKS + GEMVBLKS, 256>>>(x, W_in, W_out);

    // 0b) Phi scan (feeds GEMM1 liveness)
    dt_phi_kernel<<<NH, 256>>>(A_log, dt_bias);

    // 1) proj = x @ W_in^T — 64-row tiles, 2 CTAs/SM, dead-tile skip
    bf16_gemm_nt<<<dim3((NPROJ + 127)/128, L/64, 1), 256, GEMM_SMEM>>>(
        L, NPROJ, DM, DM, xh, xl, w1h, w1l, proj_p, ephi_p);

    // 2) conv + silu
    conv_silu_kernel<<<CONVBLKS, 256>>>(conv_w, conv_b);

    // 3) SSD pipeline with liveness early-exits
    chunk_dstate_kernel<<<dim3(NH, NC, 2), 256>>>();
    state_prefix_kernel<<<(NH*DS*HD + 255)/256, 256>>>();
    ssd_output_kernel<<<dim3(NH, NC, 2), 256>>>(Dp);

    // 4) RMS norm + gate + split
    rms_gate_kernel<<<L, 256>>>(norm_w);

    // 5) out = ybar @ W_out^T, split-K=3 + combine
    bf16_gemm_nt<<<dim3(DM/128, L/64, KSPLIT), 256, GEMM_SMEM>>>(
        L, DM, DI/KSPLIT, DI, yh, yl, w2h, w2l, outp_p, nullptr);
    combine_kernel<<<(L*DM + 255)/256, 256>>>(out);
}